// round 16
// baseline (speedup 1.0000x reference)
#include <cuda_runtime.h>
#include <math.h>

#define TT 256
#define BB 64
#define HH 512
#define G4 2048
#define MM 16384   // T*B
#define NEGV -10000.0f

typedef unsigned long long ull;

// ---------------- scratch (device globals; no allocation allowed) ----------------
__device__ float g_xg[(size_t)2*MM*G4];      // per-dir input gates (+biases): 256 MB
__device__ float g_hseq0[(size_t)MM*1024];   // layer0 output [t*64+b][hf|hb]
__device__ float g_hseq1[(size_t)MM*1024];   // layer1 output
__device__ float g_h[2*2*HH*BB];             // [parity][dir][h][b]  (transposed)
__device__ ull   g_wdup[(size_t)(2*256 + 2*1024)*2048];  // pre-dup'd transposed w_ih: 40 MB
__device__ float g_feats[MM*4];
__device__ unsigned char g_bp[TT*BB*4];
__device__ unsigned g_ctr[2][TT];            // per-(dir,step) completion counters

__device__ __forceinline__ float sigf(float x){ return 1.0f/(1.0f+expf(-x)); }

__device__ __forceinline__ ull dup2(float x){
    unsigned u = __float_as_uint(x);
    return (ull)u | ((ull)u << 32);
}
__device__ __forceinline__ float lo32(ull v){ return __uint_as_float((unsigned)v); }
__device__ __forceinline__ float hi32(ull v){ return __uint_as_float((unsigned)(v >> 32)); }

#define FFMA2(d, a, b) asm("fma.rn.f32x2 %0, %1, %2, %0;" : "+l"(d) : "l"(a), "l"(b))

__device__ __forceinline__ void cpasync16(unsigned dst, const void* src){
    asm volatile("cp.async.cg.shared.global [%0], [%1], 16;" :: "r"(dst), "l"(src));
}
#define CP_COMMIT() asm volatile("cp.async.commit_group;")
#define CP_WAIT2()  asm volatile("cp.async.wait_group 2;")

// ---------------- prep: w_ih -> transposed + f32x2-duplicated copies ----------------
__global__ void __launch_bounds__(256) prep_wdup(
    const float* __restrict__ w0f, const float* __restrict__ w0b,
    const float* __restrict__ w1f, const float* __restrict__ w1b)
{
    int z = blockIdx.y;
    const float* W = (z==0) ? w0f : (z==1) ? w0b : (z==2) ? w1f : w1b;
    int K = (z < 2) ? 256 : 1024;
    size_t base = (z==0) ? 0 : (z==1) ? (size_t)256*2048
                : (z==2) ? (size_t)512*2048 : (size_t)1536*2048;
    int idx = blockIdx.x*256 + threadIdx.x;
    if (idx >= K*2048) return;
    int k = idx % K, n = idx / K;
    g_wdup[base + (size_t)k*2048 + n] = dup2(W[(size_t)n*K + k]);
}

// ---------------- input-gate GEMM (cp.async version, unchanged) ----------------
template<bool GATHER>
__global__ void __launch_bounds__(256) xgates_kernel(
    const float* __restrict__ emb, const int* __restrict__ sent,
    const ull* __restrict__ Wdf, const ull* __restrict__ Wdb,
    const float* __restrict__ bihf, const float* __restrict__ bhhf,
    const float* __restrict__ bihb, const float* __restrict__ bhhb,
    int K)
{
    __shared__ float As[3][8][128];
    __shared__ ull   Bs[4][8][128];
    const int tid = threadIdx.x;
    const int dir = blockIdx.z;
    const ull*   Wd  = dir ? Wdb  : Wdf;
    const float* bih = dir ? bihb : bihf;
    const float* bhh = dir ? bhhb : bhhf;
    const int m_base = blockIdx.y * 128;
    const int n_base = blockIdx.x * 128;

    const int mL = tid & 127;
    const int kq = tid >> 7;
    const float* aRow;
    if (GATHER) {
        int row = m_base + mL;
        int t = row >> 6, b = row & 63;
        aRow = emb + (size_t)sent[b*TT + t] * 256;
    } else {
        aRow = g_hseq0 + (size_t)(m_base + mL) * 1024;
    }
    const ull* wsrc = Wd + n_base;

    const unsigned bs_base = (unsigned)__cvta_generic_to_shared(&Bs[0][0][0]);
    const int cA = tid, cB = tid + 256;
    const int kA = cA >> 6, npA = (cA & 63) * 2;
    const int kB = cB >> 6, npB = (cB & 63) * 2;

    const int rowg = tid & 15, colg = tid >> 4;
    const int m0 = rowg * 8, n0 = colg * 8;

    ull acc[4][8];
    #pragma unroll
    for (int p = 0; p < 4; p++)
        #pragma unroll
        for (int j = 0; j < 8; j++) acc[p][j] = 0ULL;

    const int iters = K >> 3;

    #pragma unroll
    for (int st = 0; st < 3; st++) {
        cpasync16(bs_base + (unsigned)(((st*8 + kA)*128 + npA)*8),
                  wsrc + (size_t)(st*8 + kA)*2048 + npA);
        cpasync16(bs_base + (unsigned)(((st*8 + kB)*128 + npB)*8),
                  wsrc + (size_t)(st*8 + kB)*2048 + npB);
        CP_COMMIT();
    }
    {
        float4 t0 = *(const float4*)(aRow + 0*8 + kq*4);
        As[0][kq*4+0][mL]=t0.x; As[0][kq*4+1][mL]=t0.y; As[0][kq*4+2][mL]=t0.z; As[0][kq*4+3][mL]=t0.w;
        float4 t1 = *(const float4*)(aRow + 1*8 + kq*4);
        As[1][kq*4+0][mL]=t1.x; As[1][kq*4+1][mL]=t1.y; As[1][kq*4+2][mL]=t1.z; As[1][kq*4+3][mL]=t1.w;
    }
    float4 r0 = *(const float4*)(aRow + 2*8 + kq*4);
    float4 r1 = *(const float4*)(aRow + 3*8 + kq*4);

    for (int it = 0; it < iters; it++) {
        CP_WAIT2();
        __syncthreads();
        const int bA = it % 3, bB = it & 3;

        #pragma unroll
        for (int k = 0; k < 8; k++) {
            float4 a0 = *(const float4*)&As[bA][k][m0];
            float4 a1 = *(const float4*)&As[bA][k][m0 + 4];
            ull a2[4];
            a2[0] = *(const ull*)&a0.x; a2[1] = *(const ull*)&a0.z;
            a2[2] = *(const ull*)&a1.x; a2[3] = *(const ull*)&a1.z;
            ulonglong2 b01 = *(const ulonglong2*)&Bs[bB][k][n0];
            ulonglong2 b23 = *(const ulonglong2*)&Bs[bB][k][n0 + 2];
            ulonglong2 b45 = *(const ulonglong2*)&Bs[bB][k][n0 + 4];
            ulonglong2 b67 = *(const ulonglong2*)&Bs[bB][k][n0 + 6];
            ull b2[8] = {b01.x, b01.y, b23.x, b23.y, b45.x, b45.y, b67.x, b67.y};
            #pragma unroll
            for (int p = 0; p < 4; p++)
                #pragma unroll
                for (int j = 0; j < 8; j++)
                    FFMA2(acc[p][j], a2[p], b2[j]);
        }

        if (it + 2 < iters) {
            float4 v = (it & 1) ? r1 : r0;
            int nb = (it + 2) % 3;
            As[nb][kq*4+0][mL]=v.x; As[nb][kq*4+1][mL]=v.y;
            As[nb][kq*4+2][mL]=v.z; As[nb][kq*4+3][mL]=v.w;
        }
        if (it + 4 < iters) {
            float4 nv = *(const float4*)(aRow + (it+4)*8 + kq*4);
            if (it & 1) r1 = nv; else r0 = nv;
        }
        if (it + 3 < iters) {
            int st = (it + 3) & 3;
            cpasync16(bs_base + (unsigned)(((st*8 + kA)*128 + npA)*8),
                      wsrc + (size_t)((it+3)*8 + kA)*2048 + npA);
            cpasync16(bs_base + (unsigned)(((st*8 + kB)*128 + npB)*8),
                      wsrc + (size_t)((it+3)*8 + kB)*2048 + npB);
        }
        CP_COMMIT();
    }

    float4 bi0 = *(const float4*)(bih + n_base + n0);
    float4 bi1 = *(const float4*)(bih + n_base + n0 + 4);
    float4 bh0 = *(const float4*)(bhh + n_base + n0);
    float4 bh1 = *(const float4*)(bhh + n_base + n0 + 4);
    float badd[8] = {bi0.x+bh0.x, bi0.y+bh0.y, bi0.z+bh0.z, bi0.w+bh0.w,
                     bi1.x+bh1.x, bi1.y+bh1.y, bi1.z+bh1.z, bi1.w+bh1.w};
    #pragma unroll
    for (int p = 0; p < 4; p++) {
        int r0i = m_base + m0 + 2*p;
        float ve[8], vo[8];
        #pragma unroll
        for (int j = 0; j < 8; j++) {
            ve[j] = lo32(acc[p][j]) + badd[j];
            vo[j] = hi32(acc[p][j]) + badd[j];
        }
        float* dst0 = &g_xg[((size_t)dir*MM + r0i)*G4 + n_base + n0];
        float* dst1 = &g_xg[((size_t)dir*MM + r0i + 1)*G4 + n_base + n0];
        *(float4*)(dst0)     = make_float4(ve[0], ve[1], ve[2], ve[3]);
        *(float4*)(dst0 + 4) = make_float4(ve[4], ve[5], ve[6], ve[7]);
        *(float4*)(dst1)     = make_float4(vo[0], vo[1], vo[2], vo[3]);
        *(float4*)(dst1 + 4) = make_float4(vo[4], vo[5], vo[6], vo[7]);
    }
}

// ---------------- state init: h0 -> transposed parity-0 g_h, reset step counters ----------------
__global__ void init_state(const float* __restrict__ h0, int layer)
{
    int idx = blockIdx.x * blockDim.x + threadIdx.x;
    if (idx < 2*TT) ((unsigned*)g_ctr)[idx] = 0u;
    if (idx >= 2*HH*BB) return;
    int dir = idx >> 15;
    int rem = idx & 32767;            // h*64 + b
    int h = rem >> 6, b = rem & 63;
    g_h[(size_t)dir*HH*BB + rem] = h0[((size_t)(layer*2 + dir)*BB + b)*HH + h];
}

// ---------------- persistent recurrent layer: 512 thr, 8 k-sliced pairs, A direct from L2 ----------------
// smem: Bs (W dup) 128KB | gsum [8 pairs][32 cols][68 rows] 68KB  (NO A staging)
#define SM_GS_OFF 131072
#define SM_TOT    (131072 + 69632)   // 200,704 B

// one kk-group step: FMAs read bank register directly (no MOV), refill LDG issued AFTER
#define KK_STEP(BANK, IDX, REFILL, RPTR, BOFF) do {                              \
    ull a01 = *(const ull*)&BANK[IDX].x;                                         \
    ull a23 = *(const ull*)&BANK[IDX].z;                                         \
    const ull* bb = bPtr + (BOFF)*256;                                           \
    ulonglong2 b01 = *(const ulonglong2*)(bb);                                   \
    ulonglong2 b23 = *(const ulonglong2*)(bb + 2);                               \
    ulonglong2 b45 = *(const ulonglong2*)(bb + 4);                               \
    ulonglong2 b67 = *(const ulonglong2*)(bb + 6);                               \
    FFMA2(acc0[0], a01, b01.x); FFMA2(acc0[1], a01, b01.y);                      \
    FFMA2(acc0[2], a01, b23.x); FFMA2(acc0[3], a01, b23.y);                      \
    FFMA2(acc0[4], a01, b45.x); FFMA2(acc0[5], a01, b45.y);                      \
    FFMA2(acc0[6], a01, b67.x); FFMA2(acc0[7], a01, b67.y);                      \
    FFMA2(acc1[0], a23, b01.x); FFMA2(acc1[1], a23, b01.y);                      \
    FFMA2(acc1[2], a23, b23.x); FFMA2(acc1[3], a23, b23.y);                      \
    FFMA2(acc1[4], a23, b45.x); FFMA2(acc1[5], a23, b45.y);                      \
    FFMA2(acc1[6], a23, b67.x); FFMA2(acc1[7], a23, b67.y);                      \
    if (REFILL) BANK[IDX] = __ldcg((const float4*)((RPTR) + (size_t)(IDX)*512)); \
} while(0)

__global__ void __launch_bounds__(512, 1) lstm_layer_kernel(
    const float* __restrict__ Whhf, const float* __restrict__ Whhb,
    const float* __restrict__ c0, int layer)
{
    extern __shared__ unsigned char sraw[];
    ull*   Bs   = (ull*)sraw;                       // [512][32] dup'd
    float* gsum = (float*)(sraw + SM_GS_OFF);       // [8][32][68]

    const int tid = threadIdx.x;
    const int bx  = blockIdx.x;
    const int dir = bx >> 6;
    const int ct  = bx & 63;
    const int j0  = ct * 8;
    const float* W = dir ? Whhb : Whhf;
    float* hseq = layer ? g_hseq1 : g_hseq0;

    // one-time: W slice (32 gate-cols x 512 k) duplicated into smem (512 thr)
    {
        const int c = tid >> 4;            // 0..31 : gate g=c>>3, unit u=c&7
        const int seg = tid & 15;          // 32-k segment
        const float* wp = W + (size_t)((c >> 3)*HH + j0 + (c & 7))*HH + seg*32;
        #pragma unroll
        for (int i = 0; i < 8; i++) {
            float4 v = *(const float4*)(wp + i*4);
            int k = seg*32 + i*4;
            Bs[(size_t)(k+0)*32 + c] = dup2(v.x);
            Bs[(size_t)(k+1)*32 + c] = dup2(v.y);
            Bs[(size_t)(k+2)*32 + c] = dup2(v.z);
            Bs[(size_t)(k+3)*32 + c] = dup2(v.w);
        }
    }

    // activation mapping: b_act = tid&63, u = tid>>6 (0..7): one unit per thread
    const int b_act = tid & 63;
    const int u     = tid >> 6;
    float creg = c0[((size_t)(layer*2 + dir)*BB + b_act)*HH + j0 + u];
    __syncthreads();

    // GEMM mapping: 16 warps = 8 pairs; pair p owns kk ≡ p (mod 8)
    const int lane = tid & 31, w = tid >> 5;
    const int p  = w >> 1;
    const int r0 = (w & 1)*32 + (lane & 7)*4;
    const int c0i = (lane >> 3)*8;
    float* gq = gsum + p*(32*68);

    for (int s = 0; s < TT; s++) {
        const int t = dir ? (TT-1-s) : s;
        const int parity = s & 1;
        const float* hin = g_h + ((size_t)parity*2 + dir)*HH*BB;   // [k][b]

        // prefetch activation inputs (independent of producer flags)
        const float* xr = g_xg + ((size_t)dir*MM + (size_t)t*BB + b_act)*G4 + j0 + u;
        float x_i = xr[0*HH];
        float x_f = xr[1*HH];
        float x_g = xr[2*HH];
        float x_o = xr[3*HH];

        // wait: all 64 blocks of this dir finished step s-1 (single counter line)
        if (s > 0) {
            if (tid == 0) {
                while (*(volatile unsigned*)&g_ctr[dir][s-1] < 64u) { }
                __threadfence();
            }
            __syncthreads();
        }

        // ---- GEMM: A direct from gmem (L2), 8-deep two-bank register ring ----
        ull acc0[8], acc1[8];
        #pragma unroll
        for (int j = 0; j < 8; j++) { acc0[j] = 0ULL; acc1[j] = 0ULL; }

        const float* aPtr = hin + (size_t)p*64 + r0;   // kk = 8*j + p -> offset j*512 + p*64 + r0
        float4 bank0[4], bank1[4];
        #pragma unroll
        for (int i = 0; i < 4; i++)
            bank0[i] = __ldcg((const float4*)(aPtr + (size_t)i*512));
        #pragma unroll
        for (int i = 0; i < 4; i++)
            bank1[i] = __ldcg((const float4*)(aPtr + (size_t)(4+i)*512));

        const ull* bPtr = Bs + (size_t)p*32 + c0i;     // kk stride = 32 ulls -> j stride 256

        #pragma unroll 1
        for (int jo = 0; jo < 8; jo++) {
            const float* ra = aPtr + (size_t)(8*jo + 8)*512;
            const float* rb = ra + (size_t)4*512;
            const bool more = (jo < 7);
            #pragma unroll
            for (int jj = 0; jj < 4; jj++) {
                KK_STEP(bank0, jj, more, ra, jj);
            }
            bPtr += 4*256;
            #pragma unroll
            for (int jj = 0; jj < 4; jj++) {
                KK_STEP(bank1, jj, more, rb, jj);
            }
            bPtr += 4*256;
        }

        // stash partials: gsum[p][col][row]
        #pragma unroll
        for (int j = 0; j < 8; j++) {
            *(float4*)(gq + (c0i + j)*68 + r0) =
                make_float4(lo32(acc0[j]), hi32(acc0[j]), lo32(acc1[j]), hi32(acc1[j]));
        }
        __syncthreads();

        // activations + state update: 1 unit per thread; sum 8 k-slice partials
        float* hout = g_h + ((size_t)(parity^1)*2 + dir)*HH*BB;
        float gi = x_i, gf = x_f, gg = x_g, go = x_o;
        #pragma unroll
        for (int q = 0; q < 8; q++) {
            const float* gp = gsum + q*(32*68) + b_act;
            gi += gp[( 0 + u)*68];
            gf += gp[( 8 + u)*68];
            gg += gp[(16 + u)*68];
            go += gp[(24 + u)*68];
        }
        float cn = sigf(gf)*creg + sigf(gi)*tanhf(gg);
        float hn = sigf(go)*tanhf(cn);
        creg = cn;
        hout[(j0 + u)*BB + b_act] = hn;

        // publish step completion (critical path), THEN non-critical hseq store
        __syncthreads();
        if (tid == 0) {
            __threadfence();
            atomicAdd(&g_ctr[dir][s], 1u);
        }
        hseq[((size_t)t*BB + b_act)*1024 + dir*HH + j0 + u] = hn;
    }
}

// ---------------- feats ----------------
__global__ void __launch_bounds__(128) feats_kernel(const float* __restrict__ w_out,
                                                    const float* __restrict__ b_out)
{
    __shared__ float red[128][4];
    int r = blockIdx.x, tid = threadIdx.x;
    const float* x = g_hseq1 + (size_t)r * 1024;
    float s0=0.f, s1=0.f, s2=0.f, s3=0.f;
    for (int k = tid; k < 1024; k += 128) {
        float xv = x[k];
        s0 += xv * w_out[k];
        s1 += xv * w_out[1024 + k];
        s2 += xv * w_out[2048 + k];
        s3 += xv * w_out[3072 + k];
    }
    red[tid][0]=s0; red[tid][1]=s1; red[tid][2]=s2; red[tid][3]=s3;
    __syncthreads();
    for (int off = 64; off > 0; off >>= 1) {
        if (tid < off) {
            red[tid][0]+=red[tid+off][0]; red[tid][1]+=red[tid+off][1];
            red[tid][2]+=red[tid+off][2]; red[tid][3]+=red[tid+off][3];
        }
        __syncthreads();
    }
    if (tid < 4) g_feats[r*4 + tid] = red[0][tid] + b_out[tid];
}

// ---------------- Viterbi ----------------
__global__ void viterbi_kernel(const float* __restrict__ trans, float* __restrict__ out)
{
    __shared__ float fv[64][4];
    __shared__ float tr[4][4];
    int tid = threadIdx.x;
    if (tid < 16) tr[tid>>2][tid&3] = trans[tid];
    int b = tid >> 2, nx = tid & 3;
    fv[b][nx] = (nx == 2) ? 0.0f : NEGV;   // START = 2
    __syncthreads();

    for (int t = 0; t < TT; t++) {
        float best = fv[b][0] + tr[nx][0];
        int arg = 0;
        #pragma unroll
        for (int p = 1; p < 4; p++) {
            float sc = fv[b][p] + tr[nx][p];
            if (sc > best) { best = sc; arg = p; }
        }
        float nf = best + g_feats[((size_t)t*BB + b)*4 + nx];
        g_bp[((size_t)t*BB + b)*4 + nx] = (unsigned char)arg;
        __syncthreads();
        fv[b][nx] = nf;
        __syncthreads();
    }

    if (tid < 64) {
        int bb = tid;
        float best = fv[bb][0] + tr[3][0];   // STOP = 3
        int arg = 0;
        #pragma unroll
        for (int k = 1; k < 4; k++) {
            float sc = fv[bb][k] + tr[3][k];
            if (sc > best) { best = sc; arg = k; }
        }
        out[bb] = best;
        int tag = arg;
        out[64 + bb*TT + (TT-1)] = (float)tag;
        for (int t = TT-2; t >= 0; --t) {
            tag = g_bp[((size_t)(t+1)*BB + bb)*4 + tag];
            out[64 + bb*TT + t] = (float)tag;
        }
    }
}

// ---------------- driver (9 graph nodes) ----------------
extern "C" void kernel_launch(void* const* d_in, const int* in_sizes, int n_in,
                              void* d_out, int out_size)
{
    const int*   sent  = (const int*)  d_in[0];
    const float* emb   = (const float*)d_in[1];
    const float* wih0f = (const float*)d_in[2];
    const float* whh0f = (const float*)d_in[3];
    const float* bih0f = (const float*)d_in[4];
    const float* bhh0f = (const float*)d_in[5];
    const float* wih0b = (const float*)d_in[6];
    const float* whh0b = (const float*)d_in[7];
    const float* bih0b = (const float*)d_in[8];
    const float* bhh0b = (const float*)d_in[9];
    const float* wih1f = (const float*)d_in[10];
    const float* whh1f = (const float*)d_in[11];
    const float* bih1f = (const float*)d_in[12];
    const float* bhh1f = (const float*)d_in[13];
    const float* wih1b = (const float*)d_in[14];
    const float* whh1b = (const float*)d_in[15];
    const float* bih1b = (const float*)d_in[16];
    const float* bhh1b = (const float*)d_in[17];
    const float* h0    = (const float*)d_in[18];
    const float* c0    = (const float*)d_in[19];
    const float* w_out = (const float*)d_in[20];
    const float* b_out = (const float*)d_in[21];
    const float* trans = (const float*)d_in[22];
    float* out = (float*)d_out;

    cudaFuncSetAttribute(lstm_layer_kernel,
                         cudaFuncAttributeMaxDynamicSharedMemorySize, SM_TOT);

    ull* wdup_base = nullptr;
    cudaGetSymbolAddress((void**)&wdup_base, g_wdup);
    const ull* wd0f = wdup_base;
    const ull* wd0b = wdup_base + (size_t)256*2048;
    const ull* wd1f = wdup_base + (size_t)512*2048;
    const ull* wd1b = wdup_base + (size_t)1536*2048;

    prep_wdup<<<dim3(8192, 4), 256>>>(wih0f, wih0b, wih1f, wih1b);

    dim3 gx(16, 128, 2);

    xgates_kernel<true><<<gx, 256>>>(emb, sent, wd0f, wd0b, bih0f, bhh0f, bih0b, bhh0b, 256);
    init_state<<<256, 256>>>(h0, 0);
    lstm_layer_kernel<<<128, 512, SM_TOT>>>(whh0f, whh0b, c0, 0);

    xgates_kernel<false><<<gx, 256>>>(emb, sent, wd1f, wd1b, bih1f, bhh1f, bih1b, bhh1b, 1024);
    init_state<<<256, 256>>>(h0, 1);
    lstm_layer_kernel<<<128, 512, SM_TOT>>>(whh1f, whh1b, c0, 1);

    feats_kernel<<<MM, 128>>>(w_out, b_out);
    viterbi_kernel<<<1, 256>>>(trans, out);
}

// round 17
// speedup vs baseline: 1.0639x; 1.0639x over previous
#include <cuda_runtime.h>
#include <math.h>

#define TT 256
#define BB 64
#define HH 512
#define G4 2048
#define MM 16384   // T*B
#define NEGV -10000.0f

typedef unsigned long long ull;

// ---------------- scratch (device globals; no allocation allowed) ----------------
__device__ float g_xg[(size_t)2*MM*G4];      // per-dir input gates (+biases): 256 MB
__device__ float g_hseq0[(size_t)MM*1024];   // layer0 output [t*64+b][hf|hb]
__device__ float g_hseq1[(size_t)MM*1024];   // layer1 output
__device__ float g_h[2*2*HH*BB];             // [parity][dir][h][b]  (transposed)
__device__ ull   g_wdup[(size_t)(2*256 + 2*1024)*2048];  // pre-dup'd transposed w_ih: 40 MB
__device__ float g_feats[MM*4];
__device__ unsigned char g_bp[TT*BB*4];
__device__ unsigned g_ctr[2][TT][64];        // 8 slots x 32B stride per (dir,step)

__device__ __forceinline__ float sigf(float x){ return 1.0f/(1.0f+expf(-x)); }

__device__ __forceinline__ ull dup2(float x){
    unsigned u = __float_as_uint(x);
    return (ull)u | ((ull)u << 32);
}
__device__ __forceinline__ float lo32(ull v){ return __uint_as_float((unsigned)v); }
__device__ __forceinline__ float hi32(ull v){ return __uint_as_float((unsigned)(v >> 32)); }

#define FFMA2(d, a, b) asm("fma.rn.f32x2 %0, %1, %2, %0;" : "+l"(d) : "l"(a), "l"(b))

__device__ __forceinline__ void cpasync16(unsigned dst, const void* src){
    asm volatile("cp.async.cg.shared.global [%0], [%1], 16;" :: "r"(dst), "l"(src));
}
#define CP_COMMIT() asm volatile("cp.async.commit_group;")
#define CP_WAIT2()  asm volatile("cp.async.wait_group 2;")

// ---------------- prep: w_ih -> transposed + f32x2-duplicated copies ----------------
__global__ void __launch_bounds__(256) prep_wdup(
    const float* __restrict__ w0f, const float* __restrict__ w0b,
    const float* __restrict__ w1f, const float* __restrict__ w1b)
{
    int z = blockIdx.y;
    const float* W = (z==0) ? w0f : (z==1) ? w0b : (z==2) ? w1f : w1b;
    int K = (z < 2) ? 256 : 1024;
    size_t base = (z==0) ? 0 : (z==1) ? (size_t)256*2048
                : (z==2) ? (size_t)512*2048 : (size_t)1536*2048;
    int idx = blockIdx.x*256 + threadIdx.x;
    if (idx >= K*2048) return;
    int k = idx % K, n = idx / K;
    g_wdup[base + (size_t)k*2048 + n] = dup2(W[(size_t)n*K + k]);
}

// ---------------- input-gate GEMM (cp.async; K compile-time) ----------------
template<bool GATHER, int K>
__global__ void __launch_bounds__(256) xgates_kernel(
    const float* __restrict__ emb, const int* __restrict__ sent,
    const ull* __restrict__ Wdf, const ull* __restrict__ Wdb,
    const float* __restrict__ bihf, const float* __restrict__ bhhf,
    const float* __restrict__ bihb, const float* __restrict__ bhhb)
{
    __shared__ float As[3][8][128];
    __shared__ ull   Bs[4][8][128];
    const int tid = threadIdx.x;
    const int dir = blockIdx.z;
    const ull*   Wd  = dir ? Wdb  : Wdf;
    const float* bih = dir ? bihb : bihf;
    const float* bhh = dir ? bhhb : bhhf;
    const int m_base = blockIdx.y * 128;
    const int n_base = blockIdx.x * 128;

    const int mL = tid & 127;
    const int kq = tid >> 7;
    const float* aRow;
    if (GATHER) {
        int row = m_base + mL;
        int t = row >> 6, b = row & 63;
        aRow = emb + (size_t)sent[b*TT + t] * 256;
    } else {
        aRow = g_hseq0 + (size_t)(m_base + mL) * 1024;
    }
    const ull* wsrc = Wd + n_base;

    const unsigned bs_base = (unsigned)__cvta_generic_to_shared(&Bs[0][0][0]);
    const int cA = tid, cB = tid + 256;
    const int kA = cA >> 6, npA = (cA & 63) * 2;
    const int kB = cB >> 6, npB = (cB & 63) * 2;

    const int rowg = tid & 15, colg = tid >> 4;
    const int m0 = rowg * 8, n0 = colg * 8;

    ull acc[4][8];
    #pragma unroll
    for (int p = 0; p < 4; p++)
        #pragma unroll
        for (int j = 0; j < 8; j++) acc[p][j] = 0ULL;

    constexpr int iters = K >> 3;

    #pragma unroll
    for (int st = 0; st < 3; st++) {
        cpasync16(bs_base + (unsigned)(((st*8 + kA)*128 + npA)*8),
                  wsrc + (size_t)(st*8 + kA)*2048 + npA);
        cpasync16(bs_base + (unsigned)(((st*8 + kB)*128 + npB)*8),
                  wsrc + (size_t)(st*8 + kB)*2048 + npB);
        CP_COMMIT();
    }
    {
        float4 t0 = *(const float4*)(aRow + 0*8 + kq*4);
        As[0][kq*4+0][mL]=t0.x; As[0][kq*4+1][mL]=t0.y; As[0][kq*4+2][mL]=t0.z; As[0][kq*4+3][mL]=t0.w;
        float4 t1 = *(const float4*)(aRow + 1*8 + kq*4);
        As[1][kq*4+0][mL]=t1.x; As[1][kq*4+1][mL]=t1.y; As[1][kq*4+2][mL]=t1.z; As[1][kq*4+3][mL]=t1.w;
    }
    float4 r0 = *(const float4*)(aRow + 2*8 + kq*4);
    float4 r1 = *(const float4*)(aRow + 3*8 + kq*4);

    for (int it = 0; it < iters; it++) {
        CP_WAIT2();
        __syncthreads();
        const int bA = it % 3, bB = it & 3;

        #pragma unroll
        for (int k = 0; k < 8; k++) {
            float4 a0 = *(const float4*)&As[bA][k][m0];
            float4 a1 = *(const float4*)&As[bA][k][m0 + 4];
            ull a2[4];
            a2[0] = *(const ull*)&a0.x; a2[1] = *(const ull*)&a0.z;
            a2[2] = *(const ull*)&a1.x; a2[3] = *(const ull*)&a1.z;
            ulonglong2 b01 = *(const ulonglong2*)&Bs[bB][k][n0];
            ulonglong2 b23 = *(const ulonglong2*)&Bs[bB][k][n0 + 2];
            ulonglong2 b45 = *(const ulonglong2*)&Bs[bB][k][n0 + 4];
            ulonglong2 b67 = *(const ulonglong2*)&Bs[bB][k][n0 + 6];
            ull b2[8] = {b01.x, b01.y, b23.x, b23.y, b45.x, b45.y, b67.x, b67.y};
            #pragma unroll
            for (int p = 0; p < 4; p++)
                #pragma unroll
                for (int j = 0; j < 8; j++)
                    FFMA2(acc[p][j], a2[p], b2[j]);
        }

        if (it + 2 < iters) {
            float4 v = (it & 1) ? r1 : r0;
            int nb = (it + 2) % 3;
            As[nb][kq*4+0][mL]=v.x; As[nb][kq*4+1][mL]=v.y;
            As[nb][kq*4+2][mL]=v.z; As[nb][kq*4+3][mL]=v.w;
        }
        if (it + 4 < iters) {
            float4 nv = *(const float4*)(aRow + (it+4)*8 + kq*4);
            if (it & 1) r1 = nv; else r0 = nv;
        }
        if (it + 3 < iters) {
            int st = (it + 3) & 3;
            cpasync16(bs_base + (unsigned)(((st*8 + kA)*128 + npA)*8),
                      wsrc + (size_t)((it+3)*8 + kA)*2048 + npA);
            cpasync16(bs_base + (unsigned)(((st*8 + kB)*128 + npB)*8),
                      wsrc + (size_t)((it+3)*8 + kB)*2048 + npB);
        }
        CP_COMMIT();
    }

    float4 bi0 = *(const float4*)(bih + n_base + n0);
    float4 bi1 = *(const float4*)(bih + n_base + n0 + 4);
    float4 bh0 = *(const float4*)(bhh + n_base + n0);
    float4 bh1 = *(const float4*)(bhh + n_base + n0 + 4);
    float badd[8] = {bi0.x+bh0.x, bi0.y+bh0.y, bi0.z+bh0.z, bi0.w+bh0.w,
                     bi1.x+bh1.x, bi1.y+bh1.y, bi1.z+bh1.z, bi1.w+bh1.w};
    #pragma unroll
    for (int p = 0; p < 4; p++) {
        int r0i = m_base + m0 + 2*p;
        float ve[8], vo[8];
        #pragma unroll
        for (int j = 0; j < 8; j++) {
            ve[j] = lo32(acc[p][j]) + badd[j];
            vo[j] = hi32(acc[p][j]) + badd[j];
        }
        float* dst0 = &g_xg[((size_t)dir*MM + r0i)*G4 + n_base + n0];
        float* dst1 = &g_xg[((size_t)dir*MM + r0i + 1)*G4 + n_base + n0];
        *(float4*)(dst0)     = make_float4(ve[0], ve[1], ve[2], ve[3]);
        *(float4*)(dst0 + 4) = make_float4(ve[4], ve[5], ve[6], ve[7]);
        *(float4*)(dst1)     = make_float4(vo[0], vo[1], vo[2], vo[3]);
        *(float4*)(dst1 + 4) = make_float4(vo[4], vo[5], vo[6], vo[7]);
    }
}

// ---------------- state init: h0 -> transposed parity-0 g_h, reset step counters ----------------
__global__ void init_state(const float* __restrict__ h0, int layer)
{
    int idx = blockIdx.x * blockDim.x + threadIdx.x;
    if (idx < 2*TT*64) ((unsigned*)g_ctr)[idx] = 0u;
    if (idx >= 2*HH*BB) return;
    int dir = idx >> 15;
    int rem = idx & 32767;            // h*64 + b
    int h = rem >> 6, b = rem & 63;
    g_h[(size_t)dir*HH*BB + rem] = h0[((size_t)(layer*2 + dir)*BB + b)*HH + h];
}

// ---------------- persistent recurrent layer: 256 thr, 4 k-sliced pairs, A direct from L2 ----------------
// smem: Bs (W dup) 128KB | gsum [4 pairs][32 cols][68 rows] 34KB  (NO A staging)
#define SM_GS_OFF 131072
#define SM_TOT    (131072 + 34816)

// one kk-group step: FMAs read bank register directly (no MOV), refill LDG issued AFTER
#define KK_STEP(BANK, IDX, REFILL, RPTR, BOFF) do {                              \
    ull a01 = *(const ull*)&BANK[IDX].x;                                         \
    ull a23 = *(const ull*)&BANK[IDX].z;                                         \
    const ull* bb = bPtr + (BOFF)*128;                                           \
    ulonglong2 b01 = *(const ulonglong2*)(bb);                                   \
    ulonglong2 b23 = *(const ulonglong2*)(bb + 2);                               \
    ulonglong2 b45 = *(const ulonglong2*)(bb + 4);                               \
    ulonglong2 b67 = *(const ulonglong2*)(bb + 6);                               \
    FFMA2(acc0[0], a01, b01.x); FFMA2(acc0[1], a01, b01.y);                      \
    FFMA2(acc0[2], a01, b23.x); FFMA2(acc0[3], a01, b23.y);                      \
    FFMA2(acc0[4], a01, b45.x); FFMA2(acc0[5], a01, b45.y);                      \
    FFMA2(acc0[6], a01, b67.x); FFMA2(acc0[7], a01, b67.y);                      \
    FFMA2(acc1[0], a23, b01.x); FFMA2(acc1[1], a23, b01.y);                      \
    FFMA2(acc1[2], a23, b23.x); FFMA2(acc1[3], a23, b23.y);                      \
    FFMA2(acc1[4], a23, b45.x); FFMA2(acc1[5], a23, b45.y);                      \
    FFMA2(acc1[6], a23, b67.x); FFMA2(acc1[7], a23, b67.y);                      \
    if (REFILL) BANK[IDX] = __ldcg((const float4*)((RPTR) + (size_t)(IDX)*256)); \
} while(0)

__global__ void __launch_bounds__(256, 1) lstm_layer_kernel(
    const float* __restrict__ Whhf, const float* __restrict__ Whhb,
    const float* __restrict__ c0, int layer)
{
    extern __shared__ unsigned char sraw[];
    ull*   Bs   = (ull*)sraw;                       // [512][32] dup'd
    float* gsum = (float*)(sraw + SM_GS_OFF);       // [4][32][68]

    const int tid = threadIdx.x;
    const int bx  = blockIdx.x;
    const int dir = bx >> 6;
    const int ct  = bx & 63;
    const int j0  = ct * 8;
    const float* W = dir ? Whhb : Whhf;
    float* hseq = layer ? g_hseq1 : g_hseq0;

    // one-time: W slice (32 gate-cols x 512 k) duplicated into smem
    {
        const int c = tid >> 3;            // 0..31 : gate g=c>>3, unit u=c&7
        const int seg = tid & 7;           // 64-k segment
        const float* wp = W + (size_t)((c >> 3)*HH + j0 + (c & 7))*HH + seg*64;
        #pragma unroll
        for (int i = 0; i < 16; i++) {
            float4 v = *(const float4*)(wp + i*4);
            int k = seg*64 + i*4;
            Bs[(size_t)(k+0)*32 + c] = dup2(v.x);
            Bs[(size_t)(k+1)*32 + c] = dup2(v.y);
            Bs[(size_t)(k+2)*32 + c] = dup2(v.z);
            Bs[(size_t)(k+3)*32 + c] = dup2(v.w);
        }
    }

    // activation mapping: b_act = tid&63, uq = tid>>6 (0..3); units u = uq*2 + i
    const int b_act = tid & 63;
    const int uq    = tid >> 6;
    float creg[2];
    {
        const float* cp = c0 + ((size_t)(layer*2 + dir)*BB + b_act)*HH + j0 + uq*2;
        float2 cv = *(const float2*)cp;
        creg[0]=cv.x; creg[1]=cv.y;
    }
    __syncthreads();

    // GEMM mapping: pair p = warp>>1 (k ≡ p mod 4); rowhalf = warp&1
    const int lane = tid & 31, w = tid >> 5;
    const int p  = w >> 1;
    const int r0 = (w & 1)*32 + (lane & 7)*4;
    const int c0i = (lane >> 3)*8;
    float* gq = gsum + p*(32*68);

    for (int s = 0; s < TT; s++) {
        const int t = dir ? (TT-1-s) : s;
        const int parity = s & 1;
        const float* hin = g_h + ((size_t)parity*2 + dir)*HH*BB;   // [k][b]

        // prefetch activation inputs (independent of producer flags)
        const float* xr = g_xg + ((size_t)dir*MM + (size_t)t*BB + b_act)*G4 + j0 + uq*2;
        float2 x_i = *(const float2*)(xr + 0*HH);
        float2 x_f = *(const float2*)(xr + 1*HH);
        float2 x_g = *(const float2*)(xr + 2*HH);
        float2 x_o = *(const float2*)(xr + 3*HH);

        // wait: all 64 blocks of this dir finished step s-1 (8 distributed slots)
        if (s > 0) {
            if (tid < 8) {
                while (*(volatile unsigned*)&g_ctr[dir][s-1][tid*8] < 8u) { }
                __threadfence();
            }
            __syncthreads();
        }

        // ---- GEMM: A direct from gmem (L2), 16-deep two-bank register ring ----
        ull acc0[8], acc1[8];
        #pragma unroll
        for (int j = 0; j < 8; j++) { acc0[j] = 0ULL; acc1[j] = 0ULL; }

        const float* aPtr = hin + (size_t)p*64 + r0;   // kk = 4*j + p -> offset j*256 + p*64 + r0
        float4 bank0[8], bank1[8];
        #pragma unroll
        for (int i = 0; i < 8; i++)
            bank0[i] = __ldcg((const float4*)(aPtr + (size_t)i*256));
        #pragma unroll
        for (int i = 0; i < 8; i++)
            bank1[i] = __ldcg((const float4*)(aPtr + (size_t)(8+i)*256));

        const ull* bPtr = Bs + (size_t)p*32 + c0i;

        #pragma unroll 1
        for (int jo = 0; jo < 8; jo++) {
            const float* ra = aPtr + (size_t)(16*jo + 16)*256;
            const float* rb = ra + (size_t)8*256;
            const bool more = (jo < 7);
            #pragma unroll
            for (int jj = 0; jj < 8; jj++) {
                KK_STEP(bank0, jj, more, ra, jj);
            }
            bPtr += 8*128;
            #pragma unroll
            for (int jj = 0; jj < 8; jj++) {
                KK_STEP(bank1, jj, more, rb, jj);
            }
            bPtr += 8*128;
        }

        // stash partials: gsum[p][col][row]
        #pragma unroll
        for (int j = 0; j < 8; j++) {
            *(float4*)(gq + (c0i + j)*68 + r0) =
                make_float4(lo32(acc0[j]), hi32(acc0[j]), lo32(acc1[j]), hi32(acc1[j]));
        }
        __syncthreads();

        // activations + state update: 2 consecutive units per thread; sum 4 k-slice partials
        float* hout = g_h + ((size_t)(parity^1)*2 + dir)*HH*BB;
        float xi[2] = {x_i.x, x_i.y};
        float xf[2] = {x_f.x, x_f.y};
        float xg[2] = {x_g.x, x_g.y};
        float xo[2] = {x_o.x, x_o.y};
        float hn[2];
        #pragma unroll
        for (int i = 0; i < 2; i++) {
            int u = uq*2 + i;
            float gi = xi[i], gf = xf[i], gg = xg[i], go = xo[i];
            #pragma unroll
            for (int q = 0; q < 4; q++) {
                const float* gp = gsum + q*(32*68) + b_act;
                gi += gp[( 0 + u)*68];
                gf += gp[( 8 + u)*68];
                gg += gp[(16 + u)*68];
                go += gp[(24 + u)*68];
            }
            float cn = sigf(gf)*creg[i] + sigf(gi)*tanhf(gg);
            hn[i] = sigf(go)*tanhf(cn);
            creg[i] = cn;
            hout[(j0 + u)*BB + b_act] = hn[i];
        }

        // publish step completion (critical path), THEN non-critical hseq store
        __syncthreads();
        if (tid == 0) {
            __threadfence();
            atomicAdd(&g_ctr[dir][s][(ct & 7)*8], 1u);
        }
        *(float2*)&hseq[((size_t)t*BB + b_act)*1024 + dir*HH + j0 + uq*2] =
            make_float2(hn[0], hn[1]);
    }
}

// ---------------- feats ----------------
__global__ void __launch_bounds__(128) feats_kernel(const float* __restrict__ w_out,
                                                    const float* __restrict__ b_out)
{
    __shared__ float red[128][4];
    int r = blockIdx.x, tid = threadIdx.x;
    const float* x = g_hseq1 + (size_t)r * 1024;
    float s0=0.f, s1=0.f, s2=0.f, s3=0.f;
    for (int k = tid; k < 1024; k += 128) {
        float xv = x[k];
        s0 += xv * w_out[k];
        s1 += xv * w_out[1024 + k];
        s2 += xv * w_out[2048 + k];
        s3 += xv * w_out[3072 + k];
    }
    red[tid][0]=s0; red[tid][1]=s1; red[tid][2]=s2; red[tid][3]=s3;
    __syncthreads();
    for (int off = 64; off > 0; off >>= 1) {
        if (tid < off) {
            red[tid][0]+=red[tid+off][0]; red[tid][1]+=red[tid+off][1];
            red[tid][2]+=red[tid+off][2]; red[tid][3]+=red[tid+off][3];
        }
        __syncthreads();
    }
    if (tid < 4) g_feats[r*4 + tid] = red[0][tid] + b_out[tid];
}

// ---------------- Viterbi ----------------
__global__ void viterbi_kernel(const float* __restrict__ trans, float* __restrict__ out)
{
    __shared__ float fv[64][4];
    __shared__ float tr[4][4];
    int tid = threadIdx.x;
    if (tid < 16) tr[tid>>2][tid&3] = trans[tid];
    int b = tid >> 2, nx = tid & 3;
    fv[b][nx] = (nx == 2) ? 0.0f : NEGV;   // START = 2
    __syncthreads();

    for (int t = 0; t < TT; t++) {
        float best = fv[b][0] + tr[nx][0];
        int arg = 0;
        #pragma unroll
        for (int p = 1; p < 4; p++) {
            float sc = fv[b][p] + tr[nx][p];
            if (sc > best) { best = sc; arg = p; }
        }
        float nf = best + g_feats[((size_t)t*BB + b)*4 + nx];
        g_bp[((size_t)t*BB + b)*4 + nx] = (unsigned char)arg;
        __syncthreads();
        fv[b][nx] = nf;
        __syncthreads();
    }

    if (tid < 64) {
        int bb = tid;
        float best = fv[bb][0] + tr[3][0];   // STOP = 3
        int arg = 0;
        #pragma unroll
        for (int k = 1; k < 4; k++) {
            float sc = fv[bb][k] + tr[3][k];
            if (sc > best) { best = sc; arg = k; }
        }
        out[bb] = best;
        int tag = arg;
        out[64 + bb*TT + (TT-1)] = (float)tag;
        for (int t = TT-2; t >= 0; --t) {
            tag = g_bp[((size_t)(t+1)*BB + bb)*4 + tag];
            out[64 + bb*TT + t] = (float)tag;
        }
    }
}

// ---------------- driver (9 graph nodes) ----------------
extern "C" void kernel_launch(void* const* d_in, const int* in_sizes, int n_in,
                              void* d_out, int out_size)
{
    const int*   sent  = (const int*)  d_in[0];
    const float* emb   = (const float*)d_in[1];
    const float* wih0f = (const float*)d_in[2];
    const float* whh0f = (const float*)d_in[3];
    const float* bih0f = (const float*)d_in[4];
    const float* bhh0f = (const float*)d_in[5];
    const float* wih0b = (const float*)d_in[6];
    const float* whh0b = (const float*)d_in[7];
    const float* bih0b = (const float*)d_in[8];
    const float* bhh0b = (const float*)d_in[9];
    const float* wih1f = (const float*)d_in[10];
    const float* whh1f = (const float*)d_in[11];
    const float* bih1f = (const float*)d_in[12];
    const float* bhh1f = (const float*)d_in[13];
    const float* wih1b = (const float*)d_in[14];
    const float* whh1b = (const float*)d_in[15];
    const float* bih1b = (const float*)d_in[16];
    const float* bhh1b = (const float*)d_in[17];
    const float* h0    = (const float*)d_in[18];
    const float* c0    = (const float*)d_in[19];
    const float* w_out = (const float*)d_in[20];
    const float* b_out = (const float*)d_in[21];
    const float* trans = (const float*)d_in[22];
    float* out = (float*)d_out;

    cudaFuncSetAttribute(lstm_layer_kernel,
                         cudaFuncAttributeMaxDynamicSharedMemorySize, SM_TOT);

    ull* wdup_base = nullptr;
    cudaGetSymbolAddress((void**)&wdup_base, g_wdup);
    const ull* wd0f = wdup_base;
    const ull* wd0b = wdup_base + (size_t)256*2048;
    const ull* wd1f = wdup_base + (size_t)512*2048;
    const ull* wd1b = wdup_base + (size_t)1536*2048;

    prep_wdup<<<dim3(8192, 4), 256>>>(wih0f, wih0b, wih1f, wih1b);

    dim3 gx(16, 128, 2);

    xgates_kernel<true, 256><<<gx, 256>>>(emb, sent, wd0f, wd0b, bih0f, bhh0f, bih0b, bhh0b);
    init_state<<<256, 256>>>(h0, 0);
    lstm_layer_kernel<<<128, 256, SM_TOT>>>(whh0f, whh0b, c0, 0);

    xgates_kernel<false, 1024><<<gx, 256>>>(emb, sent, wd1f, wd1b, bih1f, bhh1f, bih1b, bhh1b);
    init_state<<<256, 256>>>(h0, 1);
    lstm_layer_kernel<<<128, 256, SM_TOT>>>(whh1f, whh1b, c0, 1);

    feats_kernel<<<MM, 128>>>(w_out, b_out);
    viterbi_kernel<<<1, 256>>>(trans, out);
}